// round 5
// baseline (speedup 1.0000x reference)
#include <cuda_runtime.h>
#include <cuda_bf16.h>
#include <cstdint>
#include <math.h>

#define N_NODES 100000
#define N_EDGES 260000
#define BGRAPH  4096
#define H       300
#define H2      600
#define LAYERS  5
#define FE      16
#define BN_EPS  1e-5f
#define SCB     ((N_NODES + 1023) / 1024)   // 98 scan blocks

// ---------------- device scratch (static; no runtime allocation) --------------
__device__ float g_x[N_NODES * H];     // h (h_list[l], WITHOUT vfeat add)
__device__ float g_hp[N_NODES * H];    // (h+vfeat[gid]) @ Wn + bn_lin
__device__ float g_acc[N_NODES * H];   // aggregated pre-BN node features
__device__ float g_deg[N_NODES];
__device__ int   g_indeg[N_NODES];
__device__ int   g_cursor[N_NODES];
__device__ int   g_rowptr[N_NODES + 1];
__device__ int   g_part[SCB];
__device__ int   g_csr[N_EDGES];
__device__ int   g_gcnt[BGRAPH];
__device__ int   g_grow[BGRAPH + 1];
__device__ float g_vfeat[BGRAPH * H];
__device__ float g_vtmp[BGRAPH * H];   // also reused as z2 buffer
__device__ float g_z1[BGRAPH * H2];
__device__ float g_sum[H2];
__device__ float g_sumsq[H2];
__device__ float g_mean[H2];
__device__ float g_rstd[H2];

static inline int cdiv(int a, int b) { return (a + b - 1) / b; }

// ---------------- init ---------------------------------------------------------

__global__ void k_init0() {
    int i = blockIdx.x * blockDim.x + threadIdx.x;
    if (i < N_NODES) { g_indeg[i] = 0; g_cursor[i] = 0; }
    if (i < BGRAPH) g_gcnt[i] = 0;
}

__global__ void k_count(const int* __restrict__ dst, const int* __restrict__ gid) {
    int i = blockIdx.x * blockDim.x + threadIdx.x;
    if (i < N_EDGES) atomicAdd(&g_indeg[dst[i]], 1);
    if (i < N_NODES) atomicAdd(&g_gcnt[gid[i]], 1);
}

__global__ void k_init3(const float* __restrict__ node_emb,
                        const int* __restrict__ node_types,
                        const float* __restrict__ vn_emb) {
    int idx = blockIdx.x * blockDim.x + threadIdx.x;
    if (idx < N_NODES * H) {
        int n = idx / H, j = idx - n * H;
        g_x[idx] = node_emb[node_types[n] * H + j];
    }
    if (idx < BGRAPH * H) g_vfeat[idx] = vn_emb[idx % H];
    if (idx < N_NODES) g_deg[idx] = (float)g_indeg[idx] + 1.0f;
}

// ---------------- CSR build: scan of indeg ------------------------------------

__global__ void k_scanA() {
    __shared__ int sh[1024];
    int t = threadIdx.x;
    int idx = blockIdx.x * 1024 + t;
    sh[t] = (idx < N_NODES) ? g_indeg[idx] : 0;
    __syncthreads();
    for (int s = 512; s > 0; s >>= 1) {
        if (t < s) sh[t] += sh[t + s];
        __syncthreads();
    }
    if (t == 0) g_part[blockIdx.x] = sh[0];
}

__global__ void k_scanB() {
    int run = 0;
    for (int b = 0; b < SCB; b++) { int v = g_part[b]; g_part[b] = run; run += v; }
    g_rowptr[N_NODES] = run;
}

__global__ void k_scanC() {
    __shared__ int sh[1024];
    int t = threadIdx.x;
    int idx = blockIdx.x * 1024 + t;
    int v = (idx < N_NODES) ? g_indeg[idx] : 0;
    sh[t] = v;
    __syncthreads();
    for (int off = 1; off < 1024; off <<= 1) {
        int x = (t >= off) ? sh[t - off] : 0;
        __syncthreads();
        sh[t] += x;
        __syncthreads();
    }
    if (idx < N_NODES) g_rowptr[idx] = g_part[blockIdx.x] + sh[t] - v;
}

__global__ void k_csrfill(const int* __restrict__ dst) {
    int e = blockIdx.x * blockDim.x + threadIdx.x;
    if (e < N_EDGES) {
        int d = dst[e];
        int pos = g_rowptr[d] + atomicAdd(&g_cursor[d], 1);
        g_csr[pos] = e;
    }
}

// graph rowptr over nodes (gid is sorted): exclusive scan of g_gcnt
__global__ void k_gscan() {
    __shared__ int sh[1024];
    int t = threadIdx.x;
    int b4 = t * 4;
    int a0 = g_gcnt[b4], a1 = g_gcnt[b4 + 1], a2 = g_gcnt[b4 + 2], a3 = g_gcnt[b4 + 3];
    int s = a0 + a1 + a2 + a3;
    sh[t] = s;
    __syncthreads();
    for (int off = 1; off < 1024; off <<= 1) {
        int v = (t >= off) ? sh[t - off] : 0;
        __syncthreads();
        sh[t] += v;
        __syncthreads();
    }
    int excl = sh[t] - s;
    g_grow[b4] = excl;
    g_grow[b4 + 1] = excl + a0;
    g_grow[b4 + 2] = excl + a0 + a1;
    g_grow[b4 + 3] = excl + a0 + a1 + a2;
    if (t == 1023) g_grow[BGRAPH] = sh[1023];
}

// ---------------- virtual-node segment sum (block per graph, no atomics) -------
__global__ void k_vsum() {
    int b = blockIdx.x;
    int j = threadIdx.x;
    if (j >= H) return;
    int r0 = g_grow[b], r1 = g_grow[b + 1];
    float s = 0.f;
    for (int n = r0; n < r1; n++) s += g_x[(size_t)n * H + j];
    g_vtmp[(size_t)b * H + j] = s + (float)(r1 - r0 + 1) * g_vfeat[(size_t)b * H + j];
}

// ---------------- split3-bf16 tensor-core GEMM ---------------------------------
// C[M,N] = (A [+ vfeat[gid] gather]) @ W + bias, fp32 in/out.
// a = h + m + l (bf16 each); keep hh', hm', mh', hl', lh', mm'  (error ~2^-24)
// BM=128, BN=160, BK=16. 256 threads = 8 warps (2m x 4n), warp tile 64x40.

__device__ __forceinline__ void mma_bf16(float* c, uint32_t a0, uint32_t a1,
                                         uint32_t a2, uint32_t a3,
                                         uint32_t b0, uint32_t b1) {
    asm volatile(
        "mma.sync.aligned.m16n8k16.row.col.f32.bf16.bf16.f32 "
        "{%0,%1,%2,%3}, {%4,%5,%6,%7}, {%8,%9}, {%0,%1,%2,%3};"
        : "+f"(c[0]), "+f"(c[1]), "+f"(c[2]), "+f"(c[3])
        : "r"(a0), "r"(a1), "r"(a2), "r"(a3), "r"(b0), "r"(b1));
}

__device__ __forceinline__ void split3(float v, unsigned short& h,
                                       unsigned short& m, unsigned short& l) {
    __nv_bfloat16 hb = __float2bfloat16(v);
    float r1 = v - __bfloat162float(hb);
    __nv_bfloat16 mb = __float2bfloat16(r1);
    float r2 = r1 - __bfloat162float(mb);
    __nv_bfloat16 lb = __float2bfloat16(r2);
    h = __bfloat16_as_ushort(hb);
    m = __bfloat16_as_ushort(mb);
    l = __bfloat16_as_ushort(lb);
}

#define PADK 12   // 8 used uint32 pairs + 4 pad (conflict-free frag loads)

__global__ __launch_bounds__(256)
void k_gemm_t(const float* __restrict__ A, const float* __restrict__ W,
              const float* __restrict__ bias, float* __restrict__ C,
              int M, int K, int Ncol,
              const int* __restrict__ gid, const float* __restrict__ vfeat) {
    __shared__ uint32_t As_hi[128][PADK];
    __shared__ uint32_t As_md[128][PADK];
    __shared__ uint32_t As_lo[128][PADK];
    __shared__ uint32_t Bs_hi[160][PADK];
    __shared__ uint32_t Bs_md[160][PADK];
    __shared__ uint32_t Bs_lo[160][PADK];

    int tid = threadIdx.x;
    int warp = tid >> 5, lane = tid & 31;
    int wm = warp >> 2, wn = warp & 3;           // 2 x 4 warp grid
    int m0 = blockIdx.y * 128, n0 = blockIdx.x * 160;
    int lg = lane >> 2, lt = lane & 3;

    float acc[4][5][4];
#pragma unroll
    for (int i = 0; i < 4; i++)
#pragma unroll
        for (int j = 0; j < 5; j++)
#pragma unroll
            for (int c = 0; c < 4; c++) acc[i][j][c] = 0.f;

    int nkt = (K + 15) / 16;
    for (int kt = 0; kt < nkt; kt++) {
        int k0 = kt * 16;
        // ---- A tile: 128 rows x 8 pairs, 4 per thread ----
#pragma unroll
        for (int i = 0; i < 4; i++) {
            int f = tid + 256 * i;
            int r = f >> 3, p = f & 7;
            int gm = m0 + r, gk = k0 + 2 * p;
            float v0 = 0.f, v1 = 0.f;
            if (gm < M && gk < K) {   // K even => gk+1 < K too
                const float* ap = A + (size_t)gm * K + gk;
                v0 = ap[0]; v1 = ap[1];
                if (gid) {
                    const float* vp = vfeat + (size_t)gid[gm] * K + gk;
                    v0 += vp[0]; v1 += vp[1];
                }
            }
            unsigned short h0, m0s, l0, h1, m1s, l1;
            split3(v0, h0, m0s, l0);
            split3(v1, h1, m1s, l1);
            As_hi[r][p] = (uint32_t)h0 | ((uint32_t)h1 << 16);
            As_md[r][p] = (uint32_t)m0s | ((uint32_t)m1s << 16);
            As_lo[r][p] = (uint32_t)l0 | ((uint32_t)l1 << 16);
        }
        // ---- W tile: 160 cols x 8 pairs, 5 per thread ----
#pragma unroll
        for (int i = 0; i < 5; i++) {
            int f = tid + 256 * i;
            int n = f % 160, p = f / 160;
            int gn = n0 + n, gk = k0 + 2 * p;
            float v0 = 0.f, v1 = 0.f;
            if (gn < Ncol) {
                if (gk < K)     v0 = W[(size_t)gk * Ncol + gn];
                if (gk + 1 < K) v1 = W[(size_t)(gk + 1) * Ncol + gn];
            }
            unsigned short h0, m0s, l0, h1, m1s, l1;
            split3(v0, h0, m0s, l0);
            split3(v1, h1, m1s, l1);
            Bs_hi[n][p] = (uint32_t)h0 | ((uint32_t)h1 << 16);
            Bs_md[n][p] = (uint32_t)m0s | ((uint32_t)m1s << 16);
            Bs_lo[n][p] = (uint32_t)l0 | ((uint32_t)l1 << 16);
        }
        __syncthreads();

#pragma unroll
        for (int mt = 0; mt < 4; mt++) {
            int am = wm * 64 + mt * 16 + lg;
            uint32_t ah0 = As_hi[am][lt];
            uint32_t ah1 = As_hi[am + 8][lt];
            uint32_t ah2 = As_hi[am][4 + lt];
            uint32_t ah3 = As_hi[am + 8][4 + lt];
            uint32_t am0 = As_md[am][lt];
            uint32_t am1 = As_md[am + 8][lt];
            uint32_t am2 = As_md[am][4 + lt];
            uint32_t am3 = As_md[am + 8][4 + lt];
            uint32_t al0 = As_lo[am][lt];
            uint32_t al1 = As_lo[am + 8][lt];
            uint32_t al2 = As_lo[am][4 + lt];
            uint32_t al3 = As_lo[am + 8][4 + lt];
#pragma unroll
            for (int nt = 0; nt < 5; nt++) {
                int bn = wn * 40 + nt * 8 + lg;
                uint32_t bh0 = Bs_hi[bn][lt], bh1 = Bs_hi[bn][4 + lt];
                uint32_t bm0 = Bs_md[bn][lt], bm1 = Bs_md[bn][4 + lt];
                uint32_t bl0 = Bs_lo[bn][lt], bl1 = Bs_lo[bn][4 + lt];
                mma_bf16(acc[mt][nt], ah0, ah1, ah2, ah3, bh0, bh1);
                mma_bf16(acc[mt][nt], ah0, ah1, ah2, ah3, bm0, bm1);
                mma_bf16(acc[mt][nt], am0, am1, am2, am3, bh0, bh1);
                mma_bf16(acc[mt][nt], ah0, ah1, ah2, ah3, bl0, bl1);
                mma_bf16(acc[mt][nt], al0, al1, al2, al3, bh0, bh1);
                mma_bf16(acc[mt][nt], am0, am1, am2, am3, bm0, bm1);
            }
        }
        __syncthreads();
    }

    // ---- writeout ----
#pragma unroll
    for (int mt = 0; mt < 4; mt++) {
#pragma unroll
        for (int nt = 0; nt < 5; nt++) {
            int gn = n0 + wn * 40 + nt * 8 + 2 * lt;
            if (gn >= Ncol) continue;   // Ncol even => pair fully in-bounds
            float b0 = bias[gn], b1 = bias[gn + 1];
            int gm0 = m0 + wm * 64 + mt * 16 + lg;
            if (gm0 < M) {
                float2 o = make_float2(acc[mt][nt][0] + b0, acc[mt][nt][1] + b1);
                *(float2*)(C + (size_t)gm0 * Ncol + gn) = o;
            }
            int gm1 = gm0 + 8;
            if (gm1 < M) {
                float2 o = make_float2(acc[mt][nt][2] + b0, acc[mt][nt][3] + b1);
                *(float2*)(C + (size_t)gm1 * Ncol + gn) = o;
            }
        }
    }
}

// ---------------- fused node aggregation --------------------------------------
__global__ __launch_bounds__(256)
void k_agg(const float* __restrict__ ef, const float* __restrict__ We_l,
           const float* __restrict__ be_l, const float* __restrict__ res_l,
           const int* __restrict__ src) {
    __shared__ float Ws[FE * H];
    __shared__ float Bsh[H];
    for (int i = threadIdx.x; i < FE * H; i += 256) Ws[i] = We_l[i];
    for (int i = threadIdx.x; i < H; i += 256) Bsh[i] = be_l[i];
    __syncthreads();

    int lane = threadIdx.x & 31;
    int gw = (blockIdx.x * 256 + threadIdx.x) >> 5;
    int nw = (gridDim.x * 256) >> 5;

    float ls[10], lq[10];
#pragma unroll
    for (int t = 0; t < 10; t++) { ls[t] = 0.f; lq[t] = 0.f; }

    for (int n = gw; n < N_NODES; n += nw) {
        float dn = g_deg[n];
        float a[10];
#pragma unroll
        for (int t = 0; t < 10; t++) {
            int j = lane + 32 * t;
            a[t] = (j < H) ? fmaxf(g_hp[(size_t)n * H + j] + res_l[j], 0.f) / dn
                           : 0.f;
        }
        int e0 = g_rowptr[n], e1 = g_rowptr[n + 1];
        for (int e = e0; e < e1; e++) {
            int eid = g_csr[e];
            int s = src[eid];
            float nrm = rsqrtf(g_deg[s] * dn);
            float ev = (lane < FE) ? ef[(size_t)eid * FE + lane] : 0.f;
            float ek[16];
#pragma unroll
            for (int k = 0; k < 16; k++) ek[k] = __shfl_sync(0xffffffffu, ev, k);
            const float* hs = g_hp + (size_t)s * H;
#pragma unroll
            for (int t = 0; t < 10; t++) {
                int j = lane + 32 * t;
                if (j < H) {
                    float ep = Bsh[j];
#pragma unroll
                    for (int k = 0; k < 16; k++)
                        ep = fmaf(ek[k], Ws[k * H + j], ep);
                    a[t] += nrm * fmaxf(hs[j] + ep, 0.f);
                }
            }
        }
#pragma unroll
        for (int t = 0; t < 10; t++) {
            int j = lane + 32 * t;
            if (j < H) {
                g_acc[(size_t)n * H + j] = a[t];
                ls[t] += a[t];
                lq[t] += a[t] * a[t];
            }
        }
    }
#pragma unroll
    for (int t = 0; t < 10; t++) {
        int j = lane + 32 * t;
        if (j < H) {
            atomicAdd(&g_sum[j], ls[t]);
            atomicAdd(&g_sumsq[j], lq[t]);
        }
    }
}

// ---------------- batch norm ---------------------------------------------------

__global__ void k_zero_stats(int cols) {
    int c = blockIdx.x * blockDim.x + threadIdx.x;
    if (c < cols) { g_sum[c] = 0.0f; g_sumsq[c] = 0.0f; }
}

__global__ void k_bnstat(const float* __restrict__ X, int rows, int cols) {
    int r0 = blockIdx.x * 256;
    int rend = min(r0 + 256, rows);
    int t = threadIdx.x;
    float s[3] = {0, 0, 0}, q[3] = {0, 0, 0};
    for (int r = r0; r < rend; r++) {
        const float* row = X + (size_t)r * cols;
        int ci = 0;
        for (int c = t; c < cols; c += 256, ci++) {
            float v = row[c];
            s[ci] += v; q[ci] += v * v;
        }
    }
    int ci = 0;
    for (int c = t; c < cols; c += 256, ci++) {
        atomicAdd(&g_sum[c], s[ci]);
        atomicAdd(&g_sumsq[c], q[ci]);
    }
}

__global__ void k_bnfinal(int rows, int cols) {
    int c = blockIdx.x * blockDim.x + threadIdx.x;
    if (c < cols) {
        float m = g_sum[c] / (float)rows;
        float v = g_sumsq[c] / (float)rows - m * m;
        g_mean[c] = m;
        g_rstd[c] = rsqrtf(v + BN_EPS);
    }
}

__global__ void k_bnapply(const float* __restrict__ X, float* __restrict__ Y,
                          const float* __restrict__ gamma,
                          const float* __restrict__ beta,
                          int rows, int cols, int do_relu) {
    int idx = blockIdx.x * blockDim.x + threadIdx.x;
    if (idx < rows * cols) {
        int c = idx % cols;
        float v = (X[idx] - g_mean[c]) * g_rstd[c] * gamma[c] + beta[c];
        if (do_relu) v = fmaxf(v, 0.0f);
        Y[idx] = v;
    }
}

// ---------------- host orchestration -------------------------------------------

extern "C" void kernel_launch(void* const* d_in, const int* in_sizes, int n_in,
                              void* d_out, int out_size) {
    const int *node_types, *src, *dst, *gid;
    const float *edge_feats, *node_emb, *Wn, *bn_lin, *We, *be, *res_emb,
                *bn_gamma, *bn_beta, *vn_emb, *vW1, *vb1, *vg1, *vbt1,
                *vW2, *vb2, *vg2, *vbt2;

    if (in_sizes[0] == N_NODES) {
        node_types = (const int*)d_in[0];
        edge_feats = (const float*)d_in[1];
        src        = (const int*)d_in[2];
        dst        = (const int*)d_in[3];
        gid        = (const int*)d_in[4];
        node_emb = (const float*)d_in[6];
        Wn       = (const float*)d_in[7];
        bn_lin   = (const float*)d_in[8];
        We       = (const float*)d_in[9];
        be       = (const float*)d_in[10];
        res_emb  = (const float*)d_in[11];
        bn_gamma = (const float*)d_in[12];
        bn_beta  = (const float*)d_in[13];
        vn_emb   = (const float*)d_in[14];
        vW1  = (const float*)d_in[15];
        vb1  = (const float*)d_in[16];
        vg1  = (const float*)d_in[17];
        vbt1 = (const float*)d_in[18];
        vW2  = (const float*)d_in[19];
        vb2  = (const float*)d_in[20];
        vg2  = (const float*)d_in[21];
        vbt2 = (const float*)d_in[22];
    } else {
        edge_feats = (const float*)d_in[0];
        node_emb = (const float*)d_in[1];
        Wn       = (const float*)d_in[2];
        bn_lin   = (const float*)d_in[3];
        We       = (const float*)d_in[4];
        be       = (const float*)d_in[5];
        res_emb  = (const float*)d_in[6];
        bn_gamma = (const float*)d_in[7];
        bn_beta  = (const float*)d_in[8];
        vn_emb   = (const float*)d_in[9];
        vW1  = (const float*)d_in[10];
        vb1  = (const float*)d_in[11];
        vg1  = (const float*)d_in[12];
        vbt1 = (const float*)d_in[13];
        vW2  = (const float*)d_in[14];
        vb2  = (const float*)d_in[15];
        vg2  = (const float*)d_in[16];
        vbt2 = (const float*)d_in[17];
        node_types = (const int*)d_in[18];
        src        = (const int*)d_in[19];
        dst        = (const int*)d_in[20];
        gid        = (const int*)d_in[21];
    }

    const int NH = N_NODES * H;
    const int BH = BGRAPH * H;
    const int TPB = 256;

    float *g_x_p, *g_hp_p, *g_acc_p, *g_vtmp_p, *g_vfeat_p, *g_z1_p;
    cudaGetSymbolAddress((void**)&g_x_p, g_x);
    cudaGetSymbolAddress((void**)&g_hp_p, g_hp);
    cudaGetSymbolAddress((void**)&g_acc_p, g_acc);
    cudaGetSymbolAddress((void**)&g_vtmp_p, g_vtmp);
    cudaGetSymbolAddress((void**)&g_vfeat_p, g_vfeat);
    cudaGetSymbolAddress((void**)&g_z1_p, g_z1);

    // --- init (3 launches; 4th launch = node GEMM => lands in ncu capture slot)
    k_init0<<<cdiv(N_NODES, TPB), TPB>>>();
    k_count<<<cdiv(N_EDGES, TPB), TPB>>>(dst, gid);
    k_init3<<<cdiv(NH, TPB), TPB>>>(node_emb, node_types, vn_emb);

    dim3 node_grid(2, cdiv(N_NODES, 128));   // 320 cols cover H=300

    for (int l = 0; l < LAYERS; l++) {
        const float* Wn_l  = Wn + (size_t)l * H * H;
        const float* bnl_l = bn_lin + l * H;
        const float* We_l  = We + (size_t)l * FE * H;
        const float* be_l  = be + l * H;
        const float* res_l = res_emb + l * H;
        const float* gam_l = bn_gamma + l * H;
        const float* bet_l = bn_beta + l * H;

        // hp = (h + vfeat[gid]) @ Wn + bn_lin   (tensor cores, split3-bf16)
        k_gemm_t<<<node_grid, 256>>>(g_x_p, Wn_l, bnl_l, g_hp_p,
                                     N_NODES, H, H, gid, g_vfeat_p);

        if (l == 0) {
            // CSR + graph rowptr build (once; graph static across layers)
            k_gscan<<<1, 1024>>>();
            k_scanA<<<SCB, 1024>>>();
            k_scanB<<<1, 1>>>();
            k_scanC<<<SCB, 1024>>>();
            k_csrfill<<<cdiv(N_EDGES, TPB), TPB>>>(dst);
        }

        // virtual-node segment sum (block per graph; reads pre-update g_x)
        if (l < LAYERS - 1) k_vsum<<<BGRAPH, 320>>>();

        // fused: res init + edge messages + aggregation + BN stats
        k_zero_stats<<<cdiv(H, TPB), TPB>>>(H);
        k_agg<<<592, 256>>>(edge_feats, We_l, be_l, res_l, src);
        k_bnfinal<<<cdiv(H, TPB), TPB>>>(N_NODES, H);
        if (l < LAYERS - 1) {
            k_bnapply<<<cdiv(NH, TPB), TPB>>>(g_acc_p, g_x_p, gam_l, bet_l,
                                              N_NODES, H, 1);
        } else {
            k_bnapply<<<cdiv(NH, TPB), TPB>>>(g_acc_p, (float*)d_out, gam_l,
                                              bet_l, N_NODES, H, 0);
        }

        // virtual-node MLP update
        if (l < LAYERS - 1) {
            const float* vW1_l  = vW1 + (size_t)l * H * H2;
            const float* vb1_l  = vb1 + l * H2;
            const float* vg1_l  = vg1 + l * H2;
            const float* vbt1_l = vbt1 + l * H2;
            const float* vW2_l  = vW2 + (size_t)l * H2 * H;
            const float* vb2_l  = vb2 + l * H;
            const float* vg2_l  = vg2 + l * H;
            const float* vbt2_l = vbt2 + l * H;

            dim3 g1(4, cdiv(BGRAPH, 128));   // 640 cols cover H2=600
            k_gemm_t<<<g1, 256>>>(g_vtmp_p, vW1_l, vb1_l, g_z1_p,
                                  BGRAPH, H, H2, nullptr, nullptr);
            k_zero_stats<<<cdiv(H2, TPB), TPB>>>(H2);
            k_bnstat<<<cdiv(BGRAPH, 256), 256>>>(g_z1_p, BGRAPH, H2);
            k_bnfinal<<<cdiv(H2, TPB), TPB>>>(BGRAPH, H2);
            k_bnapply<<<cdiv(BGRAPH * H2, TPB), TPB>>>(g_z1_p, g_z1_p, vg1_l,
                                                       vbt1_l, BGRAPH, H2, 1);

            dim3 g2(2, cdiv(BGRAPH, 128));
            k_gemm_t<<<g2, 256>>>(g_z1_p, vW2_l, vb2_l, g_vtmp_p,
                                  BGRAPH, H2, H, nullptr, nullptr);
            k_zero_stats<<<cdiv(H, TPB), TPB>>>(H);
            k_bnstat<<<cdiv(BGRAPH, 256), 256>>>(g_vtmp_p, BGRAPH, H);
            k_bnfinal<<<cdiv(H, TPB), TPB>>>(BGRAPH, H);
            k_bnapply<<<cdiv(BH, TPB), TPB>>>(g_vtmp_p, g_vfeat_p, vg2_l,
                                              vbt2_l, BGRAPH, H, 1);
        }
    }
}

// round 6
// speedup vs baseline: 1.2101x; 1.2101x over previous
#include <cuda_runtime.h>
#include <cuda_bf16.h>
#include <cstdint>
#include <math.h>

#define N_NODES 100000
#define N_EDGES 260000
#define BGRAPH  4096
#define H       300
#define H2      600
#define LAYERS  5
#define FE      16
#define BN_EPS  1e-5f
#define SCB     ((N_NODES + 1023) / 1024)   // 98 scan blocks

// weight-split arena (transposed [N][K] bf16 planes)
#define WN_SEG   (H * H)            // 90000
#define VW1_SEG  (H * H2)           // 180000
#define VW2_SEG  (H2 * H)           // 180000
#define WN_BASE  0
#define VW1_BASE (LAYERS * WN_SEG)                    // 450000
#define VW2_BASE (VW1_BASE + (LAYERS - 1) * VW1_SEG)  // 1170000
#define WTOT     (VW2_BASE + (LAYERS - 1) * VW2_SEG)  // 1890000

// ---------------- device scratch (static; no runtime allocation) --------------
__device__ float g_x[N_NODES * H];     // h (h_list[l], WITHOUT vfeat add)
__device__ float g_hp[N_NODES * H];    // (h+vfeat[gid]) @ Wn + bn_lin
__device__ float g_acc[N_NODES * H];   // aggregated pre-BN node features
__device__ float g_deg[N_NODES];
__device__ int   g_indeg[N_NODES];
__device__ int   g_cursor[N_NODES];
__device__ int   g_rowptr[N_NODES + 1];
__device__ int   g_part[SCB];
__device__ int   g_csr[N_EDGES];
__device__ int   g_gcnt[BGRAPH];
__device__ int   g_grow[BGRAPH + 1];
__device__ float g_vfeat[BGRAPH * H];
__device__ float g_vtmp[BGRAPH * H];   // also reused as z2 buffer
__device__ float g_z1[BGRAPH * H2];
__device__ float g_sum[H2];
__device__ float g_sumsq[H2];
__device__ float g_mean[H2];
__device__ float g_rstd[H2];
// split planes: A (row-major [M][K]) and W (transposed [N][K])
__device__ unsigned short g_ah[N_NODES * H];
__device__ unsigned short g_amid[N_NODES * H];
__device__ unsigned short g_al[N_NODES * H];
__device__ unsigned short g_wh[WTOT];
__device__ unsigned short g_wm[WTOT];
__device__ unsigned short g_wl[WTOT];

static inline int cdiv(int a, int b) { return (a + b - 1) / b; }

__device__ __forceinline__ void split3(float v, unsigned short& h,
                                       unsigned short& m, unsigned short& l) {
    __nv_bfloat16 hb = __float2bfloat16(v);
    float r1 = v - __bfloat162float(hb);
    __nv_bfloat16 mb = __float2bfloat16(r1);
    float r2 = r1 - __bfloat162float(mb);
    __nv_bfloat16 lb = __float2bfloat16(r2);
    h = __bfloat16_as_ushort(hb);
    m = __bfloat16_as_ushort(mb);
    l = __bfloat16_as_ushort(lb);
}

// ---------------- init + weight split ------------------------------------------
// launch 1: zero counters AND split+transpose all weights (independent jobs)
__global__ void k_init0(const float* __restrict__ Wn,
                        const float* __restrict__ vW1,
                        const float* __restrict__ vW2) {
    int i = blockIdx.x * blockDim.x + threadIdx.x;
    if (i < N_NODES) { g_indeg[i] = 0; g_cursor[i] = 0; }
    if (i < BGRAPH) g_gcnt[i] = 0;
    if (i < WTOT) {
        float v;
        if (i < VW1_BASE) {                     // Wn: K=H, N=H
            int l = i / WN_SEG, r = i % WN_SEG;
            int n = r / H, k = r % H;
            v = Wn[(size_t)l * WN_SEG + k * H + n];
        } else if (i < VW2_BASE) {              // vW1: K=H, N=H2, T[H2][H]
            int e = i - VW1_BASE;
            int l = e / VW1_SEG, r = e % VW1_SEG;
            int n = r / H, k = r % H;
            v = vW1[(size_t)l * VW1_SEG + k * H2 + n];
        } else {                                // vW2: K=H2, N=H, T[H][H2]
            int e = i - VW2_BASE;
            int l = e / VW2_SEG, r = e % VW2_SEG;
            int n = r / H2, k = r % H2;
            v = vW2[(size_t)l * VW2_SEG + k * H + n];
        }
        unsigned short h, m, lo;
        split3(v, h, m, lo);
        g_wh[i] = h; g_wm[i] = m; g_wl[i] = lo;
    }
}

// launch 2
__global__ void k_count(const int* __restrict__ dst, const int* __restrict__ gid) {
    int i = blockIdx.x * blockDim.x + threadIdx.x;
    if (i < N_EDGES) atomicAdd(&g_indeg[dst[i]], 1);
    if (i < N_NODES) atomicAdd(&g_gcnt[gid[i]], 1);
}

// launch 3: h0 init + deg + vfeat + layer-0 A split (x_eff = node_emb + vn_emb)
__global__ void k_init3(const float* __restrict__ node_emb,
                        const int* __restrict__ node_types,
                        const float* __restrict__ vn_emb) {
    int idx = blockIdx.x * blockDim.x + threadIdx.x;
    if (idx < N_NODES * H) {
        int n = idx / H, j = idx - n * H;
        float hv = node_emb[node_types[n] * H + j];
        g_x[idx] = hv;
        unsigned short h, m, lo;
        split3(hv + vn_emb[j], h, m, lo);
        g_ah[idx] = h; g_amid[idx] = m; g_al[idx] = lo;
    }
    if (idx < BGRAPH * H) g_vfeat[idx] = vn_emb[idx % H];
    if (idx < N_NODES) g_deg[idx] = (float)g_indeg[idx] + 1.0f;
}

// generic A split: Xeff = X (+ vfeat[gid] gather) -> g_ah/g_amid/g_al
__global__ void k_split_a(const float* __restrict__ X, int M, int K,
                          const int* __restrict__ gid,
                          const float* __restrict__ vfeat) {
    int idx = blockIdx.x * blockDim.x + threadIdx.x;
    if (idx < M * K) {
        float v = X[idx];
        if (gid) {
            int n = idx / K, j = idx - n * K;
            v += vfeat[(size_t)gid[n] * K + j];
        }
        unsigned short h, m, lo;
        split3(v, h, m, lo);
        g_ah[idx] = h; g_amid[idx] = m; g_al[idx] = lo;
    }
}

// ---------------- CSR build ----------------------------------------------------

__global__ void k_scanA() {
    __shared__ int sh[1024];
    int t = threadIdx.x;
    int idx = blockIdx.x * 1024 + t;
    sh[t] = (idx < N_NODES) ? g_indeg[idx] : 0;
    __syncthreads();
    for (int s = 512; s > 0; s >>= 1) {
        if (t < s) sh[t] += sh[t + s];
        __syncthreads();
    }
    if (t == 0) g_part[blockIdx.x] = sh[0];
}

__global__ void k_scanB() {
    int run = 0;
    for (int b = 0; b < SCB; b++) { int v = g_part[b]; g_part[b] = run; run += v; }
    g_rowptr[N_NODES] = run;
}

__global__ void k_scanC() {
    __shared__ int sh[1024];
    int t = threadIdx.x;
    int idx = blockIdx.x * 1024 + t;
    int v = (idx < N_NODES) ? g_indeg[idx] : 0;
    sh[t] = v;
    __syncthreads();
    for (int off = 1; off < 1024; off <<= 1) {
        int x = (t >= off) ? sh[t - off] : 0;
        __syncthreads();
        sh[t] += x;
        __syncthreads();
    }
    if (idx < N_NODES) g_rowptr[idx] = g_part[blockIdx.x] + sh[t] - v;
}

__global__ void k_csrfill(const int* __restrict__ dst) {
    int e = blockIdx.x * blockDim.x + threadIdx.x;
    if (e < N_EDGES) {
        int d = dst[e];
        int pos = g_rowptr[d] + atomicAdd(&g_cursor[d], 1);
        g_csr[pos] = e;
    }
}

__global__ void k_gscan() {
    __shared__ int sh[1024];
    int t = threadIdx.x;
    int b4 = t * 4;
    int a0 = g_gcnt[b4], a1 = g_gcnt[b4 + 1], a2 = g_gcnt[b4 + 2], a3 = g_gcnt[b4 + 3];
    int s = a0 + a1 + a2 + a3;
    sh[t] = s;
    __syncthreads();
    for (int off = 1; off < 1024; off <<= 1) {
        int v = (t >= off) ? sh[t - off] : 0;
        __syncthreads();
        sh[t] += v;
        __syncthreads();
    }
    int excl = sh[t] - s;
    g_grow[b4] = excl;
    g_grow[b4 + 1] = excl + a0;
    g_grow[b4 + 2] = excl + a0 + a1;
    g_grow[b4 + 3] = excl + a0 + a1 + a2;
    if (t == 1023) g_grow[BGRAPH] = sh[1023];
}

// ---------------- virtual-node segment sum (block per graph, no atomics) -------
__global__ void k_vsum() {
    int b = blockIdx.x;
    int j = threadIdx.x;
    if (j >= H) return;
    int r0 = g_grow[b], r1 = g_grow[b + 1];
    float s = 0.f;
    for (int n = r0; n < r1; n++) s += g_x[(size_t)n * H + j];
    g_vtmp[(size_t)b * H + j] = s + (float)(r1 - r0 + 1) * g_vfeat[(size_t)b * H + j];
}

// ---------------- split3-bf16 tensor-core GEMM (pre-split operands) ------------
// C[M,N] = A @ W + bias; A planes row-major [M][K/2] u32-pairs; W planes [N][K/2]
// keep hh', hm', mh', hl', lh', mm'  (error ~2^-24)
// BM=128, BN=160, BK=16. 256 threads = 8 warps (2m x 4n), warp tile 64x40.

__device__ __forceinline__ void mma_bf16(float* c, uint32_t a0, uint32_t a1,
                                         uint32_t a2, uint32_t a3,
                                         uint32_t b0, uint32_t b1) {
    asm volatile(
        "mma.sync.aligned.m16n8k16.row.col.f32.bf16.bf16.f32 "
        "{%0,%1,%2,%3}, {%4,%5,%6,%7}, {%8,%9}, {%0,%1,%2,%3};"
        : "+f"(c[0]), "+f"(c[1]), "+f"(c[2]), "+f"(c[3])
        : "r"(a0), "r"(a1), "r"(a2), "r"(a3), "r"(b0), "r"(b1));
}

#define PADK 12   // 8 used uint32 pairs + 4 pad (conflict-free frag loads)

__global__ __launch_bounds__(256)
void k_gemm_t(const uint32_t* __restrict__ Ah, const uint32_t* __restrict__ Am,
              const uint32_t* __restrict__ Al,
              const uint32_t* __restrict__ Bh, const uint32_t* __restrict__ Bm,
              const uint32_t* __restrict__ Bl,
              const float* __restrict__ bias, float* __restrict__ C,
              int M, int K, int Ncol) {
    __shared__ uint32_t As_hi[128][PADK];
    __shared__ uint32_t As_md[128][PADK];
    __shared__ uint32_t As_lo[128][PADK];
    __shared__ uint32_t Bs_hi[160][PADK];
    __shared__ uint32_t Bs_md[160][PADK];
    __shared__ uint32_t Bs_lo[160][PADK];

    const int Kp = K >> 1;   // uint32 pairs per row (K even)
    int tid = threadIdx.x;
    int warp = tid >> 5, lane = tid & 31;
    int wm = warp >> 2, wn = warp & 3;           // 2 x 4 warp grid
    int m0 = blockIdx.y * 128, n0 = blockIdx.x * 160;
    int lg = lane >> 2, lt = lane & 3;

    float acc[4][5][4];
#pragma unroll
    for (int i = 0; i < 4; i++)
#pragma unroll
        for (int j = 0; j < 5; j++)
#pragma unroll
            for (int c = 0; c < 4; c++) acc[i][j][c] = 0.f;

    int nkt = (K + 15) / 16;
    for (int kt = 0; kt < nkt; kt++) {
        int p0 = kt * 8;
        // ---- A tile: 128 rows x 8 pairs, 4 per thread (pure u32 copies) ----
#pragma unroll
        for (int i = 0; i < 4; i++) {
            int f = tid + 256 * i;
            int r = f >> 3, p = f & 7;
            int gm = m0 + r, pp = p0 + p;
            uint32_t vh = 0, vm = 0, vl = 0;
            if (gm < M && pp < Kp) {
                size_t off = (size_t)gm * Kp + pp;
                vh = Ah[off]; vm = Am[off]; vl = Al[off];
            }
            As_hi[r][p] = vh; As_md[r][p] = vm; As_lo[r][p] = vl;
        }
        // ---- B tile: 160 cols x 8 pairs, 5 per thread ----
#pragma unroll
        for (int i = 0; i < 5; i++) {
            int f = tid + 256 * i;
            int n = f % 160, p = f / 160;
            int gn = n0 + n, pp = p0 + p;
            uint32_t vh = 0, vm = 0, vl = 0;
            if (gn < Ncol && pp < Kp) {
                size_t off = (size_t)gn * Kp + pp;
                vh = Bh[off]; vm = Bm[off]; vl = Bl[off];
            }
            Bs_hi[n][p] = vh; Bs_md[n][p] = vm; Bs_lo[n][p] = vl;
        }
        __syncthreads();

        // hoisted B fragments (30 regs)
        uint32_t bh[5][2], bm2[5][2], bl2[5][2];
#pragma unroll
        for (int nt = 0; nt < 5; nt++) {
            int bn = wn * 40 + nt * 8 + lg;
            bh[nt][0]  = Bs_hi[bn][lt]; bh[nt][1]  = Bs_hi[bn][4 + lt];
            bm2[nt][0] = Bs_md[bn][lt]; bm2[nt][1] = Bs_md[bn][4 + lt];
            bl2[nt][0] = Bs_lo[bn][lt]; bl2[nt][1] = Bs_lo[bn][4 + lt];
        }
#pragma unroll
        for (int mt = 0; mt < 4; mt++) {
            int am = wm * 64 + mt * 16 + lg;
            uint32_t ah0 = As_hi[am][lt];
            uint32_t ah1 = As_hi[am + 8][lt];
            uint32_t ah2 = As_hi[am][4 + lt];
            uint32_t ah3 = As_hi[am + 8][4 + lt];
            uint32_t am0 = As_md[am][lt];
            uint32_t am1 = As_md[am + 8][lt];
            uint32_t am2 = As_md[am][4 + lt];
            uint32_t am3 = As_md[am + 8][4 + lt];
            uint32_t al0 = As_lo[am][lt];
            uint32_t al1 = As_lo[am + 8][lt];
            uint32_t al2 = As_lo[am][4 + lt];
            uint32_t al3 = As_lo[am + 8][4 + lt];
#pragma unroll
            for (int nt = 0; nt < 5; nt++) {
                mma_bf16(acc[mt][nt], ah0, ah1, ah2, ah3, bh[nt][0], bh[nt][1]);
                mma_bf16(acc[mt][nt], ah0, ah1, ah2, ah3, bm2[nt][0], bm2[nt][1]);
                mma_bf16(acc[mt][nt], am0, am1, am2, am3, bh[nt][0], bh[nt][1]);
                mma_bf16(acc[mt][nt], ah0, ah1, ah2, ah3, bl2[nt][0], bl2[nt][1]);
                mma_bf16(acc[mt][nt], al0, al1, al2, al3, bh[nt][0], bh[nt][1]);
                mma_bf16(acc[mt][nt], am0, am1, am2, am3, bm2[nt][0], bm2[nt][1]);
            }
        }
        __syncthreads();
    }

    // ---- writeout ----
#pragma unroll
    for (int mt = 0; mt < 4; mt++) {
#pragma unroll
        for (int nt = 0; nt < 5; nt++) {
            int gn = n0 + wn * 40 + nt * 8 + 2 * lt;
            if (gn >= Ncol) continue;   // Ncol even => pair fully in-bounds
            float b0 = bias[gn], b1 = bias[gn + 1];
            int gm0 = m0 + wm * 64 + mt * 16 + lg;
            if (gm0 < M) {
                float2 o = make_float2(acc[mt][nt][0] + b0, acc[mt][nt][1] + b1);
                *(float2*)(C + (size_t)gm0 * Ncol + gn) = o;
            }
            int gm1 = gm0 + 8;
            if (gm1 < M) {
                float2 o = make_float2(acc[mt][nt][2] + b0, acc[mt][nt][3] + b1);
                *(float2*)(C + (size_t)gm1 * Ncol + gn) = o;
            }
        }
    }
}

// ---------------- fused node aggregation --------------------------------------
__global__ __launch_bounds__(256)
void k_agg(const float* __restrict__ ef, const float* __restrict__ We_l,
           const float* __restrict__ be_l, const float* __restrict__ res_l,
           const int* __restrict__ src) {
    __shared__ float Ws[FE * H];
    __shared__ float Bsh[H];
    for (int i = threadIdx.x; i < FE * H; i += 256) Ws[i] = We_l[i];
    for (int i = threadIdx.x; i < H; i += 256) Bsh[i] = be_l[i];
    __syncthreads();

    int lane = threadIdx.x & 31;
    int gw = (blockIdx.x * 256 + threadIdx.x) >> 5;
    int nw = (gridDim.x * 256) >> 5;

    float ls[10], lq[10];
#pragma unroll
    for (int t = 0; t < 10; t++) { ls[t] = 0.f; lq[t] = 0.f; }

    for (int n = gw; n < N_NODES; n += nw) {
        float dn = g_deg[n];
        float a[10];
#pragma unroll
        for (int t = 0; t < 10; t++) {
            int j = lane + 32 * t;
            a[t] = (j < H) ? fmaxf(g_hp[(size_t)n * H + j] + res_l[j], 0.f) / dn
                           : 0.f;
        }
        int e0 = g_rowptr[n], e1 = g_rowptr[n + 1];
        for (int e = e0; e < e1; e++) {
            int eid = g_csr[e];
            int s = src[eid];
            float nrm = rsqrtf(g_deg[s] * dn);
            float ev = (lane < FE) ? ef[(size_t)eid * FE + lane] : 0.f;
            float ek[16];
#pragma unroll
            for (int k = 0; k < 16; k++) ek[k] = __shfl_sync(0xffffffffu, ev, k);
            const float* hs = g_hp + (size_t)s * H;
#pragma unroll
            for (int t = 0; t < 10; t++) {
                int j = lane + 32 * t;
                if (j < H) {
                    float ep = Bsh[j];
#pragma unroll
                    for (int k = 0; k < 16; k++)
                        ep = fmaf(ek[k], Ws[k * H + j], ep);
                    a[t] += nrm * fmaxf(hs[j] + ep, 0.f);
                }
            }
        }
#pragma unroll
        for (int t = 0; t < 10; t++) {
            int j = lane + 32 * t;
            if (j < H) {
                g_acc[(size_t)n * H + j] = a[t];
                ls[t] += a[t];
                lq[t] += a[t] * a[t];
            }
        }
    }
#pragma unroll
    for (int t = 0; t < 10; t++) {
        int j = lane + 32 * t;
        if (j < H) {
            atomicAdd(&g_sum[j], ls[t]);
            atomicAdd(&g_sumsq[j], lq[t]);
        }
    }
}

// ---------------- batch norm ---------------------------------------------------

__global__ void k_zero_stats(int cols) {
    int c = blockIdx.x * blockDim.x + threadIdx.x;
    if (c < cols) { g_sum[c] = 0.0f; g_sumsq[c] = 0.0f; }
}

__global__ void k_bnstat(const float* __restrict__ X, int rows, int cols) {
    int r0 = blockIdx.x * 256;
    int rend = min(r0 + 256, rows);
    int t = threadIdx.x;
    float s[3] = {0, 0, 0}, q[3] = {0, 0, 0};
    for (int r = r0; r < rend; r++) {
        const float* row = X + (size_t)r * cols;
        int ci = 0;
        for (int c = t; c < cols; c += 256, ci++) {
            float v = row[c];
            s[ci] += v; q[ci] += v * v;
        }
    }
    int ci = 0;
    for (int c = t; c < cols; c += 256, ci++) {
        atomicAdd(&g_sum[c], s[ci]);
        atomicAdd(&g_sumsq[c], q[ci]);
    }
}

__global__ void k_bnfinal(int rows, int cols) {
    int c = blockIdx.x * blockDim.x + threadIdx.x;
    if (c < cols) {
        float m = g_sum[c] / (float)rows;
        float v = g_sumsq[c] / (float)rows - m * m;
        g_mean[c] = m;
        g_rstd[c] = rsqrtf(v + BN_EPS);
    }
}

__global__ void k_bnapply(const float* __restrict__ X, float* __restrict__ Y,
                          const float* __restrict__ gamma,
                          const float* __restrict__ beta,
                          int rows, int cols, int do_relu) {
    int idx = blockIdx.x * blockDim.x + threadIdx.x;
    if (idx < rows * cols) {
        int c = idx % cols;
        float v = (X[idx] - g_mean[c]) * g_rstd[c] * gamma[c] + beta[c];
        if (do_relu) v = fmaxf(v, 0.0f);
        Y[idx] = v;
    }
}

// ---------------- host orchestration -------------------------------------------

extern "C" void kernel_launch(void* const* d_in, const int* in_sizes, int n_in,
                              void* d_out, int out_size) {
    const int *node_types, *src, *dst, *gid;
    const float *edge_feats, *node_emb, *Wn, *bn_lin, *We, *be, *res_emb,
                *bn_gamma, *bn_beta, *vn_emb, *vW1, *vb1, *vg1, *vbt1,
                *vW2, *vb2, *vg2, *vbt2;

    if (in_sizes[0] == N_NODES) {
        node_types = (const int*)d_in[0];
        edge_feats = (const float*)d_in[1];
        src        = (const int*)d_in[2];
        dst        = (const int*)d_in[3];
        gid        = (const int*)d_in[4];
        node_emb = (const float*)d_in[6];
        Wn       = (const float*)d_in[7];
        bn_lin   = (const float*)d_in[8];
        We       = (const float*)d_in[9];
        be       = (const float*)d_in[10];
        res_emb  = (const float*)d_in[11];
        bn_gamma = (const float*)d_in[12];
        bn_beta  = (const float*)d_in[13];
        vn_emb   = (const float*)d_in[14];
        vW1  = (const float*)d_in[15];
        vb1  = (const float*)d_in[16];
        vg1  = (const float*)d_in[17];
        vbt1 = (const float*)d_in[18];
        vW2  = (const float*)d_in[19];
        vb2  = (const float*)d_in[20];
        vg2  = (const float*)d_in[21];
        vbt2 = (const float*)d_in[22];
    } else {
        edge_feats = (const float*)d_in[0];
        node_emb = (const float*)d_in[1];
        Wn       = (const float*)d_in[2];
        bn_lin   = (const float*)d_in[3];
        We       = (const float*)d_in[4];
        be       = (const float*)d_in[5];
        res_emb  = (const float*)d_in[6];
        bn_gamma = (const float*)d_in[7];
        bn_beta  = (const float*)d_in[8];
        vn_emb   = (const float*)d_in[9];
        vW1  = (const float*)d_in[10];
        vb1  = (const float*)d_in[11];
        vg1  = (const float*)d_in[12];
        vbt1 = (const float*)d_in[13];
        vW2  = (const float*)d_in[14];
        vb2  = (const float*)d_in[15];
        vg2  = (const float*)d_in[16];
        vbt2 = (const float*)d_in[17];
        node_types = (const int*)d_in[18];
        src        = (const int*)d_in[19];
        dst        = (const int*)d_in[20];
        gid        = (const int*)d_in[21];
    }

    const int NH = N_NODES * H;
    const int BH = BGRAPH * H;
    const int TPB = 256;

    float *g_x_p, *g_hp_p, *g_acc_p, *g_vtmp_p, *g_vfeat_p, *g_z1_p;
    cudaGetSymbolAddress((void**)&g_x_p, g_x);
    cudaGetSymbolAddress((void**)&g_hp_p, g_hp);
    cudaGetSymbolAddress((void**)&g_acc_p, g_acc);
    cudaGetSymbolAddress((void**)&g_vtmp_p, g_vtmp);
    cudaGetSymbolAddress((void**)&g_vfeat_p, g_vfeat);
    cudaGetSymbolAddress((void**)&g_z1_p, g_z1);
    unsigned short *ah_p, *am_p, *al_p, *wh_p, *wm_p, *wl_p;
    cudaGetSymbolAddress((void**)&ah_p, g_ah);
    cudaGetSymbolAddress((void**)&am_p, g_amid);
    cudaGetSymbolAddress((void**)&al_p, g_al);
    cudaGetSymbolAddress((void**)&wh_p, g_wh);
    cudaGetSymbolAddress((void**)&wm_p, g_wm);
    cudaGetSymbolAddress((void**)&wl_p, g_wl);
    const uint32_t* Ah = (const uint32_t*)ah_p;
    const uint32_t* Am = (const uint32_t*)am_p;
    const uint32_t* Al = (const uint32_t*)al_p;

    // --- init (3 launches; 4th = node GEMM -> lands in ncu capture slot) ---
    k_init0<<<cdiv(WTOT, TPB), TPB>>>(Wn, vW1, vW2);
    k_count<<<cdiv(N_EDGES, TPB), TPB>>>(dst, gid);
    k_init3<<<cdiv(NH, TPB), TPB>>>(node_emb, node_types, vn_emb);

    dim3 node_grid(2, cdiv(N_NODES, 128));   // 320 cols cover H=300

    for (int l = 0; l < LAYERS; l++) {
        const float* bnl_l = bn_lin + l * H;
        const float* We_l  = We + (size_t)l * FE * H;
        const float* be_l  = be + l * H;
        const float* res_l = res_emb + l * H;
        const float* gam_l = bn_gamma + l * H;
        const float* bet_l = bn_beta + l * H;
        const uint32_t* Wnh = (const uint32_t*)(wh_p + WN_BASE + (size_t)l * WN_SEG);
        const uint32_t* Wnm = (const uint32_t*)(wm_p + WN_BASE + (size_t)l * WN_SEG);
        const uint32_t* Wnl = (const uint32_t*)(wl_p + WN_BASE + (size_t)l * WN_SEG);

        // hp = (h + vfeat[gid]) @ Wn + bn_lin   (A split done previous step)
        k_gemm_t<<<node_grid, 256>>>(Ah, Am, Al, Wnh, Wnm, Wnl,
                                     bnl_l, g_hp_p, N_NODES, H, H);

        if (l == 0) {
            // CSR + graph rowptr build (once; graph static across layers)
            k_gscan<<<1, 1024>>>();
            k_scanA<<<SCB, 1024>>>();
            k_scanB<<<1, 1>>>();
            k_scanC<<<SCB, 1024>>>();
            k_csrfill<<<cdiv(N_EDGES, TPB), TPB>>>(dst);
        }

        // virtual-node segment sum (block per graph; reads pre-update g_x)
        if (l < LAYERS - 1) k_vsum<<<BGRAPH, 320>>>();

        // fused: res init + edge messages + aggregation + BN stats
        k_zero_stats<<<cdiv(H, TPB), TPB>>>(H);
        k_agg<<<592, 256>>>(edge_feats, We_l, be_l, res_l, src);
        k_bnfinal<<<cdiv(H, TPB), TPB>>>(N_NODES, H);
        if (l < LAYERS - 1) {
            k_bnapply<<<cdiv(NH, TPB), TPB>>>(g_acc_p, g_x_p, gam_l, bet_l,
                                              N_NODES, H, 1);
        } else {
            k_bnapply<<<cdiv(NH, TPB), TPB>>>(g_acc_p, (float*)d_out, gam_l,
                                              bet_l, N_NODES, H, 0);
        }

        // virtual-node MLP update
        if (l < LAYERS - 1) {
            const float* vb1_l  = vb1 + l * H2;
            const float* vg1_l  = vg1 + l * H2;
            const float* vbt1_l = vbt1 + l * H2;
            const float* vb2_l  = vb2 + l * H;
            const float* vg2_l  = vg2 + l * H;
            const float* vbt2_l = vbt2 + l * H;
            const uint32_t* W1h = (const uint32_t*)(wh_p + VW1_BASE + (size_t)l * VW1_SEG);
            const uint32_t* W1m = (const uint32_t*)(wm_p + VW1_BASE + (size_t)l * VW1_SEG);
            const uint32_t* W1l = (const uint32_t*)(wl_p + VW1_BASE + (size_t)l * VW1_SEG);
            const uint32_t* W2h = (const uint32_t*)(wh_p + VW2_BASE + (size_t)l * VW2_SEG);
            const uint32_t* W2m = (const uint32_t*)(wm_p + VW2_BASE + (size_t)l * VW2_SEG);
            const uint32_t* W2l = (const uint32_t*)(wl_p + VW2_BASE + (size_t)l * VW2_SEG);

            // z1 = vtmp @ vW1 + vb1
            k_split_a<<<cdiv(BH, TPB), TPB>>>(g_vtmp_p, BGRAPH, H, nullptr, nullptr);
            dim3 g1(4, cdiv(BGRAPH, 128));
            k_gemm_t<<<g1, 256>>>(Ah, Am, Al, W1h, W1m, W1l,
                                  vb1_l, g_z1_p, BGRAPH, H, H2);
            k_zero_stats<<<cdiv(H2, TPB), TPB>>>(H2);
            k_bnstat<<<cdiv(BGRAPH, 256), 256>>>(g_z1_p, BGRAPH, H2);
            k_bnfinal<<<cdiv(H2, TPB), TPB>>>(BGRAPH, H2);
            k_bnapply<<<cdiv(BGRAPH * H2, TPB), TPB>>>(g_z1_p, g_z1_p, vg1_l,
                                                       vbt1_l, BGRAPH, H2, 1);

            // z2 = z1 @ vW2 + vb2
            k_split_a<<<cdiv(BGRAPH * H2, TPB), TPB>>>(g_z1_p, BGRAPH, H2, nullptr, nullptr);
            dim3 g2(2, cdiv(BGRAPH, 128));
            k_gemm_t<<<g2, 256>>>(Ah, Am, Al, W2h, W2m, W2l,
                                  vb2_l, g_vtmp_p, BGRAPH, H2, H);
            k_zero_stats<<<cdiv(H, TPB), TPB>>>(H);
            k_bnstat<<<cdiv(BGRAPH, 256), 256>>>(g_vtmp_p, BGRAPH, H);
            k_bnfinal<<<cdiv(H, TPB), TPB>>>(BGRAPH, H);
            k_bnapply<<<cdiv(BH, TPB), TPB>>>(g_vtmp_p, g_vfeat_p, vg2_l,
                                              vbt2_l, BGRAPH, H, 1);

            // A split for next layer's node GEMM (after bnapply wrote g_x)
            k_split_a<<<cdiv(NH, TPB), TPB>>>(g_x_p, N_NODES, H, gid, g_vfeat_p);
        }
    }
}

// round 7
// speedup vs baseline: 1.4295x; 1.1813x over previous
#include <cuda_runtime.h>
#include <cuda_bf16.h>
#include <cstdint>
#include <math.h>

#define N_NODES 100000
#define N_EDGES 260000
#define BGRAPH  4096
#define H       300
#define H2      600
#define LAYERS  5
#define FE      16
#define BN_EPS  1e-5f
#define SCB     ((N_NODES + 1023) / 1024)

// weight-split arena (transposed [N][K] bf16 planes)
#define WN_SEG   (H * H)
#define VW1_SEG  (H * H2)
#define VW2_SEG  (H2 * H)
#define WN_BASE  0
#define VW1_BASE (LAYERS * WN_SEG)
#define VW2_BASE (VW1_BASE + (LAYERS - 1) * VW1_SEG)
#define WTOT     (VW2_BASE + (LAYERS - 1) * VW2_SEG)

// ---------------- device scratch -----------------------------------------------
__device__ float g_x[N_NODES * H];
__device__ float g_hp[N_NODES * H];
__device__ float g_acc[N_NODES * H];
__device__ float g_deg[N_NODES];
__device__ int   g_indeg[N_NODES];
__device__ int   g_cursor[N_NODES];
__device__ int   g_rowptr[N_NODES + 1];
__device__ int   g_part[SCB];
__device__ int   g_csr[N_EDGES];
__device__ int   g_csrc[N_EDGES];      // CSR-ordered src node
__device__ float g_enorm[N_EDGES];     // CSR-ordered rsqrt(deg_s*deg_d)
__device__ float g_cef[N_EDGES * FE];  // CSR-ordered edge feats
__device__ int   g_gcnt[BGRAPH];
__device__ int   g_grow[BGRAPH + 1];
__device__ float g_vfeat[BGRAPH * H];
__device__ float g_vtmp[BGRAPH * H];   // z2 float buffer
__device__ float g_z1[BGRAPH * H2];
__device__ float g_sum[H2];
__device__ float g_sumsq[H2];
__device__ float g_mean[H2];
__device__ float g_rstd[H2];
// split planes
__device__ unsigned short g_ah[N_NODES * H];
__device__ unsigned short g_amid[N_NODES * H];
__device__ unsigned short g_al[N_NODES * H];
__device__ unsigned short g_vah[BGRAPH * H2];
__device__ unsigned short g_vam[BGRAPH * H2];
__device__ unsigned short g_val[BGRAPH * H2];
__device__ unsigned short g_wh[WTOT];
__device__ unsigned short g_wm[WTOT];
__device__ unsigned short g_wl[WTOT];

static inline int cdiv(int a, int b) { return (a + b - 1) / b; }

__device__ __forceinline__ void split3(float v, unsigned short& h,
                                       unsigned short& m, unsigned short& l) {
    __nv_bfloat16 hb = __float2bfloat16(v);
    float r1 = v - __bfloat162float(hb);
    __nv_bfloat16 mb = __float2bfloat16(r1);
    float r2 = r1 - __bfloat162float(mb);
    __nv_bfloat16 lb = __float2bfloat16(r2);
    h = __bfloat16_as_ushort(hb);
    m = __bfloat16_as_ushort(mb);
    l = __bfloat16_as_ushort(lb);
}

// ---------------- init + weight split ------------------------------------------
__global__ void k_init0(const float* __restrict__ Wn,
                        const float* __restrict__ vW1,
                        const float* __restrict__ vW2) {
    int i = blockIdx.x * blockDim.x + threadIdx.x;
    if (i < N_NODES) { g_indeg[i] = 0; g_cursor[i] = 0; }
    if (i < BGRAPH) g_gcnt[i] = 0;
    if (i < WTOT) {
        float v;
        if (i < VW1_BASE) {
            int l = i / WN_SEG, r = i % WN_SEG;
            int n = r / H, k = r % H;
            v = Wn[(size_t)l * WN_SEG + k * H + n];
        } else if (i < VW2_BASE) {
            int e = i - VW1_BASE;
            int l = e / VW1_SEG, r = e % VW1_SEG;
            int n = r / H, k = r % H;
            v = vW1[(size_t)l * VW1_SEG + k * H2 + n];
        } else {
            int e = i - VW2_BASE;
            int l = e / VW2_SEG, r = e % VW2_SEG;
            int n = r / H2, k = r % H2;
            v = vW2[(size_t)l * VW2_SEG + k * H + n];
        }
        unsigned short h, m, lo;
        split3(v, h, m, lo);
        g_wh[i] = h; g_wm[i] = m; g_wl[i] = lo;
    }
}

__global__ void k_count(const int* __restrict__ dst, const int* __restrict__ gid) {
    int i = blockIdx.x * blockDim.x + threadIdx.x;
    if (i < N_EDGES) atomicAdd(&g_indeg[dst[i]], 1);
    if (i < N_NODES) atomicAdd(&g_gcnt[gid[i]], 1);
}

__global__ void k_init3(const float* __restrict__ node_emb,
                        const int* __restrict__ node_types,
                        const float* __restrict__ vn_emb) {
    int idx = blockIdx.x * blockDim.x + threadIdx.x;
    if (idx < N_NODES * H) {
        int n = idx / H, j = idx - n * H;
        float hv = node_emb[node_types[n] * H + j];
        g_x[idx] = hv;
        unsigned short h, m, lo;
        split3(hv + vn_emb[j], h, m, lo);
        g_ah[idx] = h; g_amid[idx] = m; g_al[idx] = lo;
    }
    if (idx < BGRAPH * H) g_vfeat[idx] = vn_emb[idx % H];
    if (idx < N_NODES) g_deg[idx] = (float)g_indeg[idx] + 1.0f;
}

// ---------------- CSR build ----------------------------------------------------

__global__ void k_scanA() {
    __shared__ int sh[1024];
    int t = threadIdx.x;
    int idx = blockIdx.x * 1024 + t;
    sh[t] = (idx < N_NODES) ? g_indeg[idx] : 0;
    __syncthreads();
    for (int s = 512; s > 0; s >>= 1) {
        if (t < s) sh[t] += sh[t + s];
        __syncthreads();
    }
    if (t == 0) g_part[blockIdx.x] = sh[0];
}

__global__ void k_scanB() {
    int run = 0;
    for (int b = 0; b < SCB; b++) { int v = g_part[b]; g_part[b] = run; run += v; }
    g_rowptr[N_NODES] = run;
}

__global__ void k_scanC() {
    __shared__ int sh[1024];
    int t = threadIdx.x;
    int idx = blockIdx.x * 1024 + t;
    int v = (idx < N_NODES) ? g_indeg[idx] : 0;
    sh[t] = v;
    __syncthreads();
    for (int off = 1; off < 1024; off <<= 1) {
        int x = (t >= off) ? sh[t - off] : 0;
        __syncthreads();
        sh[t] += x;
        __syncthreads();
    }
    if (idx < N_NODES) g_rowptr[idx] = g_part[blockIdx.x] + sh[t] - v;
}

__global__ void k_csrfill(const int* __restrict__ dst) {
    int e = blockIdx.x * blockDim.x + threadIdx.x;
    if (e < N_EDGES) {
        int d = dst[e];
        int pos = g_rowptr[d] + atomicAdd(&g_cursor[d], 1);
        g_csr[pos] = e;
    }
}

// CSR-ordered edge data (one time): src, norm, edge feats
__global__ void k_csrdata(const int* __restrict__ src, const int* __restrict__ dst,
                          const float* __restrict__ ef) {
    int idx = blockIdx.x * blockDim.x + threadIdx.x;
    if (idx < N_EDGES) {
        int eid = g_csr[idx];
        int s = src[eid];
        g_csrc[idx] = s;
        g_enorm[idx] = rsqrtf(g_deg[s] * g_deg[dst[eid]]);
    }
    if (idx < N_EDGES * FE) {
        int pos = idx >> 4, k = idx & 15;
        g_cef[idx] = ef[(size_t)g_csr[pos] * FE + k];
    }
}

__global__ void k_gscan() {
    __shared__ int sh[1024];
    int t = threadIdx.x;
    int b4 = t * 4;
    int a0 = g_gcnt[b4], a1 = g_gcnt[b4 + 1], a2 = g_gcnt[b4 + 2], a3 = g_gcnt[b4 + 3];
    int s = a0 + a1 + a2 + a3;
    sh[t] = s;
    __syncthreads();
    for (int off = 1; off < 1024; off <<= 1) {
        int v = (t >= off) ? sh[t - off] : 0;
        __syncthreads();
        sh[t] += v;
        __syncthreads();
    }
    int excl = sh[t] - s;
    g_grow[b4] = excl;
    g_grow[b4 + 1] = excl + a0;
    g_grow[b4 + 2] = excl + a0 + a1;
    g_grow[b4 + 3] = excl + a0 + a1 + a2;
    if (t == 1023) g_grow[BGRAPH] = sh[1023];
}

// ---------------- virtual-node segment sum -> split planes directly ------------
__global__ void k_vsum() {
    int b = blockIdx.x;
    int j = threadIdx.x;
    if (j >= H) return;
    int r0 = g_grow[b], r1 = g_grow[b + 1];
    float s = 0.f;
    for (int n = r0; n < r1; n++) s += g_x[(size_t)n * H + j];
    float v = s + (float)(r1 - r0 + 1) * g_vfeat[(size_t)b * H + j];
    unsigned short h, m, lo;
    split3(v, h, m, lo);
    size_t o = (size_t)b * H + j;
    g_vah[o] = h; g_vam[o] = m; g_val[o] = lo;
}

// ---------------- split3-bf16 tensor-core GEMM (register-pipelined) ------------
__device__ __forceinline__ void mma_bf16(float* c, uint32_t a0, uint32_t a1,
                                         uint32_t a2, uint32_t a3,
                                         uint32_t b0, uint32_t b1) {
    asm volatile(
        "mma.sync.aligned.m16n8k16.row.col.f32.bf16.bf16.f32 "
        "{%0,%1,%2,%3}, {%4,%5,%6,%7}, {%8,%9}, {%0,%1,%2,%3};"
        : "+f"(c[0]), "+f"(c[1]), "+f"(c[2]), "+f"(c[3])
        : "r"(a0), "r"(a1), "r"(a2), "r"(a3), "r"(b0), "r"(b1));
}

#define PADK 12

__global__ __launch_bounds__(256)
void k_gemm_t(const uint32_t* __restrict__ Ah, const uint32_t* __restrict__ Am,
              const uint32_t* __restrict__ Al,
              const uint32_t* __restrict__ Bh, const uint32_t* __restrict__ Bm,
              const uint32_t* __restrict__ Bl,
              const float* __restrict__ bias, float* __restrict__ C,
              int M, int K, int Ncol) {
    __shared__ uint32_t As_hi[128][PADK];
    __shared__ uint32_t As_md[128][PADK];
    __shared__ uint32_t As_lo[128][PADK];
    __shared__ uint32_t Bs_hi[160][PADK];
    __shared__ uint32_t Bs_md[160][PADK];
    __shared__ uint32_t Bs_lo[160][PADK];

    const int Kp = K >> 1;
    int tid = threadIdx.x;
    int warp = tid >> 5, lane = tid & 31;
    int wm = warp >> 2, wn = warp & 3;
    int m0 = blockIdx.y * 128, n0 = blockIdx.x * 160;
    int lg = lane >> 2, lt = lane & 3;

    // per-thread load coords (fixed)
    int ar = tid >> 3, ap = tid & 7;          // +32 rows per i
    int bn_ = tid % 160, bp0 = tid / 160;     // +256 flat per i

    float acc[4][5][4];
#pragma unroll
    for (int i = 0; i < 4; i++)
#pragma unroll
        for (int j = 0; j < 5; j++)
#pragma unroll
            for (int c = 0; c < 4; c++) acc[i][j][c] = 0.f;

    uint32_t pa[4][3], pb[5][3];
    int nkt = (K + 15) / 16;

    // prologue: prefetch tile 0
    {
        int p0 = 0;
#pragma unroll
        for (int i = 0; i < 4; i++) {
            int gm = m0 + ar + 32 * i, pp = p0 + ap;
            pa[i][0] = pa[i][1] = pa[i][2] = 0;
            if (gm < M && pp < Kp) {
                size_t off = (size_t)gm * Kp + pp;
                pa[i][0] = Ah[off]; pa[i][1] = Am[off]; pa[i][2] = Al[off];
            }
        }
#pragma unroll
        for (int i = 0; i < 5; i++) {
            int f = tid + 256 * i;
            int n = f % 160, p = f / 160;
            int gn = n0 + n, pp = p0 + p;
            pb[i][0] = pb[i][1] = pb[i][2] = 0;
            if (gn < Ncol && pp < Kp) {
                size_t off = (size_t)gn * Kp + pp;
                pb[i][0] = Bh[off]; pb[i][1] = Bm[off]; pb[i][2] = Bl[off];
            }
        }
    }

    for (int kt = 0; kt < nkt; kt++) {
        __syncthreads();
        // store prefetched tile
#pragma unroll
        for (int i = 0; i < 4; i++) {
            int r = ar + 32 * i;
            As_hi[r][ap] = pa[i][0]; As_md[r][ap] = pa[i][1]; As_lo[r][ap] = pa[i][2];
        }
#pragma unroll
        for (int i = 0; i < 5; i++) {
            int f = tid + 256 * i;
            int n = f % 160, p = f / 160;
            Bs_hi[n][p] = pb[i][0]; Bs_md[n][p] = pb[i][1]; Bs_lo[n][p] = pb[i][2];
        }
        __syncthreads();

        // prefetch next tile (overlaps MMA below)
        if (kt + 1 < nkt) {
            int p0 = (kt + 1) * 8;
#pragma unroll
            for (int i = 0; i < 4; i++) {
                int gm = m0 + ar + 32 * i, pp = p0 + ap;
                pa[i][0] = pa[i][1] = pa[i][2] = 0;
                if (gm < M && pp < Kp) {
                    size_t off = (size_t)gm * Kp + pp;
                    pa[i][0] = Ah[off]; pa[i][1] = Am[off]; pa[i][2] = Al[off];
                }
            }
#pragma unroll
            for (int i = 0; i < 5; i++) {
                int f = tid + 256 * i;
                int n = f % 160, p = f / 160;
                int gn = n0 + n, pp = p0 + p;
                pb[i][0] = pb[i][1] = pb[i][2] = 0;
                if (gn < Ncol && pp < Kp) {
                    size_t off = (size_t)gn * Kp + pp;
                    pb[i][0] = Bh[off]; pb[i][1] = Bm[off]; pb[i][2] = Bl[off];
                }
            }
        }

        // compute
        uint32_t bh[5][2], bm2[5][2], bl2[5][2];
#pragma unroll
        for (int nt = 0; nt < 5; nt++) {
            int bn2 = wn * 40 + nt * 8 + lg;
            bh[nt][0]  = Bs_hi[bn2][lt]; bh[nt][1]  = Bs_hi[bn2][4 + lt];
            bm2[nt][0] = Bs_md[bn2][lt]; bm2[nt][1] = Bs_md[bn2][4 + lt];
            bl2[nt][0] = Bs_lo[bn2][lt]; bl2[nt][1] = Bs_lo[bn2][4 + lt];
        }
#pragma unroll
        for (int mt = 0; mt < 4; mt++) {
            int am = wm * 64 + mt * 16 + lg;
            uint32_t ah0 = As_hi[am][lt];
            uint32_t ah1 = As_hi[am + 8][lt];
            uint32_t ah2 = As_hi[am][4 + lt];
            uint32_t ah3 = As_hi[am + 8][4 + lt];
            uint32_t am0 = As_md[am][lt];
            uint32_t am1 = As_md[am + 8][lt];
            uint32_t am2 = As_md[am][4 + lt];
            uint32_t am3 = As_md[am + 8][4 + lt];
            uint32_t al0 = As_lo[am][lt];
            uint32_t al1 = As_lo[am + 8][lt];
            uint32_t al2 = As_lo[am][4 + lt];
            uint32_t al3 = As_lo[am + 8][4 + lt];
#pragma unroll
            for (int nt = 0; nt < 5; nt++) {
                mma_bf16(acc[mt][nt], ah0, ah1, ah2, ah3, bh[nt][0], bh[nt][1]);
                mma_bf16(acc[mt][nt], ah0, ah1, ah2, ah3, bm2[nt][0], bm2[nt][1]);
                mma_bf16(acc[mt][nt], am0, am1, am2, am3, bh[nt][0], bh[nt][1]);
                mma_bf16(acc[mt][nt], ah0, ah1, ah2, ah3, bl2[nt][0], bl2[nt][1]);
                mma_bf16(acc[mt][nt], al0, al1, al2, al3, bh[nt][0], bh[nt][1]);
                mma_bf16(acc[mt][nt], am0, am1, am2, am3, bm2[nt][0], bm2[nt][1]);
            }
        }
    }

    // writeout
#pragma unroll
    for (int mt = 0; mt < 4; mt++) {
#pragma unroll
        for (int nt = 0; nt < 5; nt++) {
            int gn = n0 + wn * 40 + nt * 8 + 2 * lt;
            if (gn >= Ncol) continue;
            float b0 = bias[gn], b1 = bias[gn + 1];
            int gm0 = m0 + wm * 64 + mt * 16 + lg;
            if (gm0 < M) {
                float2 o = make_float2(acc[mt][nt][0] + b0, acc[mt][nt][1] + b1);
                *(float2*)(C + (size_t)gm0 * Ncol + gn) = o;
            }
            int gm1 = gm0 + 8;
            if (gm1 < M) {
                float2 o = make_float2(acc[mt][nt][2] + b0, acc[mt][nt][3] + b1);
                *(float2*)(C + (size_t)gm1 * Ncol + gn) = o;
            }
        }
    }
}

// ---------------- fused node aggregation (CSR-ordered edge data) ----------------
__global__ __launch_bounds__(256)
void k_agg(const float* __restrict__ be_l, const float* __restrict__ We_l,
           const float* __restrict__ res_l) {
    __shared__ float Ws[FE * H];
    __shared__ float Bsh[H];
    for (int i = threadIdx.x; i < FE * H; i += 256) Ws[i] = We_l[i];
    for (int i = threadIdx.x; i < H; i += 256) Bsh[i] = be_l[i];
    __syncthreads();

    int lane = threadIdx.x & 31;
    int gw = (blockIdx.x * 256 + threadIdx.x) >> 5;
    int nw = (gridDim.x * 256) >> 5;

    float ls[10], lq[10];
#pragma unroll
    for (int t = 0; t < 10; t++) { ls[t] = 0.f; lq[t] = 0.f; }

    for (int n = gw; n < N_NODES; n += nw) {
        float dn = g_deg[n];
        float a[10];
#pragma unroll
        for (int t = 0; t < 10; t++) {
            int j = lane + 32 * t;
            a[t] = (j < H) ? fmaxf(g_hp[(size_t)n * H + j] + res_l[j], 0.f) / dn
                           : 0.f;
        }
        int e0 = g_rowptr[n], e1 = g_rowptr[n + 1];
        for (int e = e0; e < e1; e++) {
            int s = g_csrc[e];
            float nrm = g_enorm[e];
            float ev = (lane < FE) ? g_cef[(size_t)e * FE + lane] : 0.f;
            float ek[16];
#pragma unroll
            for (int k = 0; k < 16; k++) ek[k] = __shfl_sync(0xffffffffu, ev, k);
            const float* hs = g_hp + (size_t)s * H;
#pragma unroll
            for (int t = 0; t < 10; t++) {
                int j = lane + 32 * t;
                if (j < H) {
                    float ep = Bsh[j];
#pragma unroll
                    for (int k = 0; k < 16; k++)
                        ep = fmaf(ek[k], Ws[k * H + j], ep);
                    a[t] += nrm * fmaxf(hs[j] + ep, 0.f);
                }
            }
        }
#pragma unroll
        for (int t = 0; t < 10; t++) {
            int j = lane + 32 * t;
            if (j < H) {
                g_acc[(size_t)n * H + j] = a[t];
                ls[t] += a[t];
                lq[t] += a[t] * a[t];
            }
        }
    }
#pragma unroll
    for (int t = 0; t < 10; t++) {
        int j = lane + 32 * t;
        if (j < H) {
            atomicAdd(&g_sum[j], ls[t]);
            atomicAdd(&g_sumsq[j], lq[t]);
        }
    }
}

// ---------------- batch norm ---------------------------------------------------

__global__ void k_zero_stats(int cols) {
    int c = blockIdx.x * blockDim.x + threadIdx.x;
    if (c < cols) { g_sum[c] = 0.0f; g_sumsq[c] = 0.0f; }
}

__global__ void k_bnstat(const float* __restrict__ X, int rows, int cols) {
    int r0 = blockIdx.x * 256;
    int rend = min(r0 + 256, rows);
    int t = threadIdx.x;
    float s[3] = {0, 0, 0}, q[3] = {0, 0, 0};
    for (int r = r0; r < rend; r++) {
        const float* row = X + (size_t)r * cols;
        int ci = 0;
        for (int c = t; c < cols; c += 256, ci++) {
            float v = row[c];
            s[ci] += v; q[ci] += v * v;
        }
    }
    int ci = 0;
    for (int c = t; c < cols; c += 256, ci++) {
        atomicAdd(&g_sum[c], s[ci]);
        atomicAdd(&g_sumsq[c], q[ci]);
    }
}

__global__ void k_bnfinal(int rows, int cols) {
    int c = blockIdx.x * blockDim.x + threadIdx.x;
    if (c < cols) {
        float m = g_sum[c] / (float)rows;
        float v = g_sumsq[c] / (float)rows - m * m;
        g_mean[c] = m;
        g_rstd[c] = rsqrtf(v + BN_EPS);
    }
}

// BN apply + optional float output + optional split-plane output (+vfeat gather)
__global__ void k_bnap(const float* __restrict__ X, float* __restrict__ Y,
                       const float* __restrict__ gamma,
                       const float* __restrict__ beta,
                       int rows, int cols, int do_relu,
                       unsigned short* __restrict__ ph,
                       unsigned short* __restrict__ pm,
                       unsigned short* __restrict__ pl,
                       const int* __restrict__ gid,
                       const float* __restrict__ vfeat) {
    int idx = blockIdx.x * blockDim.x + threadIdx.x;
    if (idx < rows * cols) {
        int c = idx % cols;
        float v = (X[idx] - g_mean[c]) * g_rstd[c] * gamma[c] + beta[c];
        if (do_relu) v = fmaxf(v, 0.0f);
        if (Y) Y[idx] = v;
        if (ph) {
            float p = v;
            if (gid) p += vfeat[(size_t)gid[idx / cols] * cols + c];
            unsigned short h, m, lo;
            split3(p, h, m, lo);
            ph[idx] = h; pm[idx] = m; pl[idx] = lo;
        }
    }
}

// ---------------- host orchestration -------------------------------------------

extern "C" void kernel_launch(void* const* d_in, const int* in_sizes, int n_in,
                              void* d_out, int out_size) {
    const int *node_types, *src, *dst, *gid;
    const float *edge_feats, *node_emb, *Wn, *bn_lin, *We, *be, *res_emb,
                *bn_gamma, *bn_beta, *vn_emb, *vW1, *vb1, *vg1, *vbt1,
                *vW2, *vb2, *vg2, *vbt2;

    if (in_sizes[0] == N_NODES) {
        node_types = (const int*)d_in[0];
        edge_feats = (const float*)d_in[1];
        src        = (const int*)d_in[2];
        dst        = (const int*)d_in[3];
        gid        = (const int*)d_in[4];
        node_emb = (const float*)d_in[6];
        Wn       = (const float*)d_in[7];
        bn_lin   = (const float*)d_in[8];
        We       = (const float*)d_in[9];
        be       = (const float*)d_in[10];
        res_emb  = (const float*)d_in[11];
        bn_gamma = (const float*)d_in[12];
        bn_beta  = (const float*)d_in[13];
        vn_emb   = (const float*)d_in[14];
        vW1  = (const float*)d_in[15];
        vb1  = (const float*)d_in[16];
        vg1  = (const float*)d_in[17];
        vbt1 = (const float*)d_in[18];
        vW2  = (const float*)d_in[19];
        vb2  = (const float*)d_in[20];
        vg2  = (const float*)d_in[21];
        vbt2 = (const float*)d_in[22];
    } else {
        edge_feats = (const float*)d_in[0];
        node_emb = (const float*)d_in[1];
        Wn       = (const float*)d_in[2];
        bn_lin   = (const float*)d_in[3];
        We       = (const float*)d_in[4];
        be       = (const float*)d_in[5];
        res_emb  = (const float*)d_in[6];
        bn_gamma = (const float*)d_in[7];
        bn_beta  = (const float*)d_in[8];
        vn_emb   = (const float*)d_in[9];
        vW1  = (const float*)d_in[10];
        vb1  = (const float*)d_in[11];
        vg1  = (const float*)d_in[12];
        vbt1 = (const float*)d_in[13];
        vW2  = (const float*)d_in[14];
        vb2  = (const float*)d_in[15];
        vg2  = (const float*)d_in[16];
        vbt2 = (const float*)d_in[17];
        node_types = (const int*)d_in[18];
        src        = (const int*)d_in[19];
        dst        = (const int*)d_in[20];
        gid        = (const int*)d_in[21];
    }

    const int NH = N_NODES * H;
    const int BH = BGRAPH * H;
    const int TPB = 256;

    float *g_x_p, *g_hp_p, *g_acc_p, *g_vtmp_p, *g_vfeat_p, *g_z1_p;
    cudaGetSymbolAddress((void**)&g_x_p, g_x);
    cudaGetSymbolAddress((void**)&g_hp_p, g_hp);
    cudaGetSymbolAddress((void**)&g_acc_p, g_acc);
    cudaGetSymbolAddress((void**)&g_vtmp_p, g_vtmp);
    cudaGetSymbolAddress((void**)&g_vfeat_p, g_vfeat);
    cudaGetSymbolAddress((void**)&g_z1_p, g_z1);
    unsigned short *ah_p, *am_p, *al_p, *vah_p, *vam_p, *val_p, *wh_p, *wm_p, *wl_p;
    cudaGetSymbolAddress((void**)&ah_p, g_ah);
    cudaGetSymbolAddress((void**)&am_p, g_amid);
    cudaGetSymbolAddress((void**)&al_p, g_al);
    cudaGetSymbolAddress((void**)&vah_p, g_vah);
    cudaGetSymbolAddress((void**)&vam_p, g_vam);
    cudaGetSymbolAddress((void**)&val_p, g_val);
    cudaGetSymbolAddress((void**)&wh_p, g_wh);
    cudaGetSymbolAddress((void**)&wm_p, g_wm);
    cudaGetSymbolAddress((void**)&wl_p, g_wl);
    const uint32_t* Ah = (const uint32_t*)ah_p;
    const uint32_t* Am = (const uint32_t*)am_p;
    const uint32_t* Al = (const uint32_t*)al_p;
    const uint32_t* VAh = (const uint32_t*)vah_p;
    const uint32_t* VAm = (const uint32_t*)vam_p;
    const uint32_t* VAl = (const uint32_t*)val_p;

    k_init0<<<cdiv(WTOT, TPB), TPB>>>(Wn, vW1, vW2);
    k_count<<<cdiv(N_EDGES, TPB), TPB>>>(dst, gid);
    k_init3<<<cdiv(NH, TPB), TPB>>>(node_emb, node_types, vn_emb);

    dim3 node_grid(2, cdiv(N_NODES, 128));

    for (int l = 0; l < LAYERS; l++) {
        const float* bnl_l = bn_lin + l * H;
        const float* We_l  = We + (size_t)l * FE * H;
        const float* be_l  = be + l * H;
        const float* res_l = res_emb + l * H;
        const float* gam_l = bn_gamma + l * H;
        const float* bet_l = bn_beta + l * H;
        const uint32_t* Wnh = (const uint32_t*)(wh_p + WN_BASE + (size_t)l * WN_SEG);
        const uint32_t* Wnm = (const uint32_t*)(wm_p + WN_BASE + (size_t)l * WN_SEG);
        const uint32_t* Wnl = (const uint32_t*)(wl_p + WN_BASE + (size_t)l * WN_SEG);

        // hp = (h + vfeat[gid]) @ Wn + bn_lin
        k_gemm_t<<<node_grid, 256>>>(Ah, Am, Al, Wnh, Wnm, Wnl,
                                     bnl_l, g_hp_p, N_NODES, H, H);

        if (l == 0) {
            k_gscan<<<1, 1024>>>();
            k_scanA<<<SCB, 1024>>>();
            k_scanB<<<1, 1>>>();
            k_scanC<<<SCB, 1024>>>();
            k_csrfill<<<cdiv(N_EDGES, TPB), TPB>>>(dst);
            k_csrdata<<<cdiv(N_EDGES * FE, TPB), TPB>>>(src, dst, edge_feats);
        }

        if (l < LAYERS - 1) {
            const float* vb1_l  = vb1 + l * H2;
            const float* vg1_l  = vg1 + l * H2;
            const float* vbt1_l = vbt1 + l * H2;
            const float* vb2_l  = vb2 + l * H;
            const float* vg2_l  = vg2 + l * H;
            const float* vbt2_l = vbt2 + l * H;
            const uint32_t* W1h = (const uint32_t*)(wh_p + VW1_BASE + (size_t)l * VW1_SEG);
            const uint32_t* W1m = (const uint32_t*)(wm_p + VW1_BASE + (size_t)l * VW1_SEG);
            const uint32_t* W1l = (const uint32_t*)(wl_p + VW1_BASE + (size_t)l * VW1_SEG);
            const uint32_t* W2h = (const uint32_t*)(wh_p + VW2_BASE + (size_t)l * VW2_SEG);
            const uint32_t* W2m = (const uint32_t*)(wm_p + VW2_BASE + (size_t)l * VW2_SEG);
            const uint32_t* W2l = (const uint32_t*)(wl_p + VW2_BASE + (size_t)l * VW2_SEG);

            // vtmp planes = split(segsum(h) + (cnt+1)*vfeat)
            k_vsum<<<BGRAPH, 320>>>();

            // z1 = vtmp @ vW1 + vb1 -> BN+relu -> vplanes (H2 stride)
            dim3 g1(4, cdiv(BGRAPH, 128));
            k_gemm_t<<<g1, 256>>>(VAh, VAm, VAl, W1h, W1m, W1l,
                                  vb1_l, g_z1_p, BGRAPH, H, H2);
            k_zero_stats<<<cdiv(H2, TPB), TPB>>>(H2);
            k_bnstat<<<cdiv(BGRAPH, 256), 256>>>(g_z1_p, BGRAPH, H2);
            k_bnfinal<<<cdiv(H2, TPB), TPB>>>(BGRAPH, H2);
            k_bnap<<<cdiv(BGRAPH * H2, TPB), TPB>>>(g_z1_p, nullptr, vg1_l, vbt1_l,
                                                    BGRAPH, H2, 1,
                                                    vah_p, vam_p, val_p,
                                                    nullptr, nullptr);

            // z2 = z1 @ vW2 + vb2 -> BN+relu -> new vfeat
            dim3 g2(2, cdiv(BGRAPH, 128));
            k_gemm_t<<<g2, 256>>>(VAh, VAm, VAl, W2h, W2m, W2l,
                                  vb2_l, g_vtmp_p, BGRAPH, H2, H);
            k_zero_stats<<<cdiv(H, TPB), TPB>>>(H);
            k_bnstat<<<cdiv(BGRAPH, 256), 256>>>(g_vtmp_p, BGRAPH, H);
            k_bnfinal<<<cdiv(H, TPB), TPB>>>(BGRAPH, H);
            k_bnap<<<cdiv(BH, TPB), TPB>>>(g_vtmp_p, g_vfeat_p, vg2_l, vbt2_l,
                                           BGRAPH, H, 1,
                                           nullptr, nullptr, nullptr,
                                           nullptr, nullptr);
        }

        // node aggregation + BN stats
        k_zero_stats<<<cdiv(H, TPB), TPB>>>(H);
        k_agg<<<1184, 256>>>(be_l, We_l, res_l);
        k_bnfinal<<<cdiv(H, TPB), TPB>>>(N_NODES, H);

        if (l < LAYERS - 1) {
            // h_{l+1} float + next-layer A planes (with NEW vfeat gather)
            k_bnap<<<cdiv(NH, TPB), TPB>>>(g_acc_p, g_x_p, gam_l, bet_l,
                                           N_NODES, H, 1,
                                           ah_p, am_p, al_p, gid, g_vfeat_p);
        } else {
            k_bnap<<<cdiv(NH, TPB), TPB>>>(g_acc_p, (float*)d_out, gam_l, bet_l,
                                           N_NODES, H, 0,
                                           nullptr, nullptr, nullptr,
                                           nullptr, nullptr);
        }
    }
}